// round 7
// baseline (speedup 1.0000x reference)
#include <cuda_runtime.h>
#include <math.h>

#define NBATCH 4
#define NHID   128
#define NCOL   65536
#define NMODE  256

// Scratch (allocation-free rule: device globals)
__device__ __align__(16) float g_y[2 * NBATCH * NHID * NMODE];  // [ri][b][k][m] 1 MB
__device__ __align__(16) float g_z[(size_t)NHID * NCOL];        // 33.5 MB: z[k][n]
//   n <  256 : raw  c[k,n] + lin_b[k]
//   n >= 256 : gelu(c[k,n] + lin_b[k])

__device__ __forceinline__ float gelu_exact(float v) {
    return 0.5f * v * (1.0f + erff(v * 0.70710678118654752440f));
}

// ---- packed f32x2 helpers (SASS FFMA2; PTX-only path on sm_103a) ----------
__device__ __forceinline__ unsigned long long pack2_dup(float v) {
    unsigned long long r;
    unsigned int u = __float_as_uint(v);
    asm("mov.b64 %0, {%1, %1};" : "=l"(r) : "r"(u));
    return r;
}
__device__ __forceinline__ void fma2(unsigned long long& d,
                                     unsigned long long a, unsigned long long b) {
    asm("fma.rn.f32x2 %0, %1, %2, %0;" : "+l"(d) : "l"(a), "l"(b));
}
__device__ __forceinline__ float2 unpack2(unsigned long long v) {
    unsigned int lo, hi;
    asm("mov.b64 {%0, %1}, %2;" : "=r"(lo), "=r"(hi) : "l"(v));
    return make_float2(__uint_as_float(lo), __uint_as_float(hi));
}

// ---------------------------------------------------------------------------
// Kernel A: per-mode GEMM, NO h-split, NO partials. b-split CTAs instead:
//   g_y[ri][b][k][m] = sum_{h=0..127} x[b,h,m] * w_{ri}[h,k,m]
// grid (32 = 8 kb * 4 b [b fastest], 8 mb, 2 ri) = 512 CTAs, 128 threads.
// All CTAs resident; the 4 b-CTAs per tile stream identical w addresses
// concurrently -> L2 dedups, DRAM sees w once (33.5 MB).
// ---------------------------------------------------------------------------
__global__ void __launch_bounds__(128) kmodes(const float* __restrict__ x,
                                              const float* __restrict__ wr,
                                              const float* __restrict__ wi) {
    __shared__ float xs[NHID * 32];           // [h][m(32)] 16 KB, one batch
    const int kb = blockIdx.x >> 2, b = blockIdx.x & 3;
    const int mb = blockIdx.y, ri = blockIdx.z;
    const float* w = ri ? wi : wr;
    const int m0 = mb * 32, k0 = kb * 16;
    const int tid = threadIdx.x;

    for (int i = tid; i < NHID * 8; i += 128) {
        int j = i & 7;
        int h = i >> 3;
        float4 v = *reinterpret_cast<const float4*>(
            x + (size_t)(b * NHID + h) * NCOL + m0 + j * 4);
        *reinterpret_cast<float4*>(xs + h * 32 + j * 4) = v;
    }
    __syncthreads();

    const int kl = tid & 15;      // 16 k per CTA
    const int mg = tid >> 4;      // 8 m-quads
    const int k  = k0 + kl;
    const int mm = mg * 4;

    float a0 = 0.f, a1 = 0.f, a2 = 0.f, a3 = 0.f;
    const float* wp = w + (size_t)k * NMODE + m0 + mm;   // + h*NHID*NMODE
#pragma unroll 8
    for (int h = 0; h < NHID; h++) {
        float4 wv = __ldg(reinterpret_cast<const float4*>(wp + (size_t)h * NHID * NMODE));
        float4 xv = *reinterpret_cast<const float4*>(xs + h * 32 + mm);
        a0 += xv.x * wv.x;
        a1 += xv.y * wv.y;
        a2 += xv.z * wv.z;
        a3 += xv.w * wv.w;
    }
    *reinterpret_cast<float4*>(
        &g_y[((ri * NBATCH + b) * NHID + k) * NMODE + m0 + mm]) =
        make_float4(a0, a1, a2, a3);
}

// ---------------------------------------------------------------------------
// Kernel B: c[k,n] = sum_h lin_w[k,h]*bias[h,n] via FFMA2 -> g_z only.
//   n >= 256: g_z = gelu(c + lin_b[k]);   n < 256: g_z = c + lin_b[k] (raw)
// grid (1024 nb, 2 kb) = 2048 CTAs, 256 threads (16 kt x 16 nt),
// 4k (2 packed pairs) x 4n per thread. 68 KB smem -> 3 CTAs/SM.
// ---------------------------------------------------------------------------
#define WPITCH 68   // 64 k-cols + pad; 272 B rows keep 16 B alignment
__global__ void __launch_bounds__(256, 3) kgemm(const float* __restrict__ bias,
                                                const float* __restrict__ lin_w,
                                                const float* __restrict__ lin_b) {
    extern __shared__ float sm[];
    float* wT = sm;                      // [h][k(64)] pitch 68
    float* sb = sm + NHID * WPITCH;      // [h][64]
    __shared__ float slb[64];

    const int tid = threadIdx.x;
    const int n_base = blockIdx.x * 64;
    const int kbase  = blockIdx.y * 64;

    // stage lin_w transposed (64 k-rows)
    for (int i = tid; i < 64 * NHID; i += 256) {
        int h = i & 127, k = i >> 7;
        wT[h * WPITCH + k] = lin_w[(kbase + k) * NHID + h];
    }
    if (tid < 64) slb[tid] = lin_b[kbase + tid];
    for (int i = tid; i < NHID * 16; i += 256) {
        int h = i >> 4, j = i & 15;
        float4 v = *reinterpret_cast<const float4*>(bias + (size_t)h * NCOL + n_base + j * 4);
        *reinterpret_cast<float4*>(sb + h * 64 + j * 4) = v;
    }
    __syncthreads();

    const int kt = tid >> 4;     // 0..15 -> 4 k each (2 packed pairs)
    const int nt = tid & 15;     // 0..15 -> 4 n each

    unsigned long long acc2[2][4];   // [k-pair][n]
#pragma unroll
    for (int p = 0; p < 2; p++)
#pragma unroll
        for (int j = 0; j < 4; j++) acc2[p][j] = 0ULL;

    const float* wrow = wT + kt * 4;
    const float* bp = sb + nt * 4;
#pragma unroll 4
    for (int h = 0; h < NHID; h++) {
        float4 bv = *reinterpret_cast<const float4*>(bp + h * 64);
        ulonglong2 wA = *reinterpret_cast<const ulonglong2*>(wrow + h * WPITCH);
        unsigned long long bn0 = pack2_dup(bv.x);
        unsigned long long bn1 = pack2_dup(bv.y);
        unsigned long long bn2 = pack2_dup(bv.z);
        unsigned long long bn3 = pack2_dup(bv.w);
        fma2(acc2[0][0], wA.x, bn0); fma2(acc2[0][1], wA.x, bn1);
        fma2(acc2[0][2], wA.x, bn2); fma2(acc2[0][3], wA.x, bn3);
        fma2(acc2[1][0], wA.y, bn0); fma2(acc2[1][1], wA.y, bn1);
        fma2(acc2[1][2], wA.y, bn2); fma2(acc2[1][3], wA.y, bn3);
    }

    const int n0 = n_base + nt * 4;
    const bool far = (n_base >= NMODE);
#pragma unroll
    for (int p = 0; p < 2; p++) {
        int kk = kt * 4 + 2 * p;
        float lb0 = slb[kk], lb1 = slb[kk + 1];
        float2 a0 = unpack2(acc2[p][0]);
        float2 a1 = unpack2(acc2[p][1]);
        float2 a2 = unpack2(acc2[p][2]);
        float2 a3 = unpack2(acc2[p][3]);
        float4 r0 = make_float4(a0.x + lb0, a1.x + lb0, a2.x + lb0, a3.x + lb0);
        float4 r1 = make_float4(a0.y + lb1, a1.y + lb1, a2.y + lb1, a3.y + lb1);
        if (far) {
            r0 = make_float4(gelu_exact(r0.x), gelu_exact(r0.y), gelu_exact(r0.z), gelu_exact(r0.w));
            r1 = make_float4(gelu_exact(r1.x), gelu_exact(r1.y), gelu_exact(r1.z), gelu_exact(r1.w));
        }
        *reinterpret_cast<float4*>(&g_z[(size_t)(kbase + kk) * NCOL + n0]) = r0;
        *reinterpret_cast<float4*>(&g_z[(size_t)(kbase + kk + 1) * NCOL + n0]) = r1;
    }
}

// ---------------------------------------------------------------------------
// Kernel W: streaming expander for n >= 256.
//   out[b,k,n,0] = g_z[k,n]; out[b,k,n,1] = 0.
// grid (64, 128, 4), 256 threads; 1 float4 read (L2-hot), 2 STG.128/thread.
// ---------------------------------------------------------------------------
__global__ void __launch_bounds__(256) kwrite(float* __restrict__ out) {
    const int k = blockIdx.y;
    const int b = blockIdx.z;
    const int idx = blockIdx.x * 256 + threadIdx.x;   // float4 index past n=256
    if (idx >= (NCOL - NMODE) / 4) return;
    const int n0 = NMODE + idx * 4;
    float4 z = *reinterpret_cast<const float4*>(&g_z[(size_t)k * NCOL + n0]);
    float4 lo = make_float4(z.x, 0.f, z.y, 0.f);
    float4 hi = make_float4(z.z, 0.f, z.w, 0.f);
    float* op = out + 2 * ((size_t)(b * NHID + k) * NCOL + n0);
    __stcs(reinterpret_cast<float4*>(op),     lo);
    __stcs(reinterpret_cast<float4*>(op + 4), hi);
}

// ---------------------------------------------------------------------------
// Kernel C: n < 256 region (reads tiny L2-hot g_y directly).
//   out[b,k,n,0] = gelu(sum_h lin_w[k,h]*y_r + g_z[k,n]); out[...,1] = gelu(..y_i)
// grid 128 = (8 m-tiles of 32) x (4 b) x (4 k-blocks of 32), 256 threads
// ---------------------------------------------------------------------------
__global__ void __launch_bounds__(256) ksmall(const float* __restrict__ lin_w,
                                              float* __restrict__ out) {
    extern __shared__ float smc[];
    float* sW = smc;               // [32][129]
    float* sy = smc + 32 * 129;    // [ri*128+h][32]
    const int bx = blockIdx.x;
    const int mt = bx & 7, b = (bx >> 3) & 3, kb = bx >> 5;
    const int tid = threadIdx.x;
    const int m0 = mt * 32;

    for (int i = tid; i < 32 * NHID; i += 256) {
        int h = i & 127, r = i >> 7;
        sW[r * 129 + h] = lin_w[(kb * 32 + r) * NHID + h];
    }
    for (int i = tid; i < 2 * NHID * 8; i += 256) {
        int j = i & 7;
        int rh = i >> 3;                 // ri*128 + h
        int ri = rh >> 7, h = rh & 127;
        float4 v = *reinterpret_cast<const float4*>(
            &g_y[((ri * NBATCH + b) * NHID + h) * NMODE + m0 + j * 4]);
        *reinterpret_cast<float4*>(sy + rh * 32 + j * 4) = v;
    }
    __syncthreads();

    const int kl = tid >> 3;   // 0..31
    const int ng = tid & 7;
    const int k = kb * 32 + kl;

    float ar[4] = {0.f, 0.f, 0.f, 0.f};
    float ai[4] = {0.f, 0.f, 0.f, 0.f};
    const float* wp  = sW + kl * 129;
    const float* yrp = sy + ng * 4;
    const float* yip = sy + NHID * 32 + ng * 4;
#pragma unroll 4
    for (int h = 0; h < NHID; h++) {
        float w = wp[h];
        float4 r4 = *reinterpret_cast<const float4*>(yrp + h * 32);
        float4 i4 = *reinterpret_cast<const float4*>(yip + h * 32);
        ar[0] += w * r4.x; ar[1] += w * r4.y; ar[2] += w * r4.z; ar[3] += w * r4.w;
        ai[0] += w * i4.x; ai[1] += w * i4.y; ai[2] += w * i4.z; ai[3] += w * i4.w;
    }
    const int n0 = m0 + ng * 4;
    float4 cv = *reinterpret_cast<const float4*>(&g_z[(size_t)k * NCOL + n0]);
    float4 lo = make_float4(gelu_exact(ar[0] + cv.x), gelu_exact(ai[0]),
                            gelu_exact(ar[1] + cv.y), gelu_exact(ai[1]));
    float4 hi = make_float4(gelu_exact(ar[2] + cv.z), gelu_exact(ai[2]),
                            gelu_exact(ar[3] + cv.w), gelu_exact(ai[3]));
    float* op = out + 2 * ((size_t)(b * NHID + k) * NCOL + n0);
    *reinterpret_cast<float4*>(op)     = lo;
    *reinterpret_cast<float4*>(op + 4) = hi;
}

// ---------------------------------------------------------------------------
extern "C" void kernel_launch(void* const* d_in, const int* in_sizes, int n_in,
                              void* d_out, int out_size) {
    const float* x     = (const float*)d_in[0];
    const float* wr    = (const float*)d_in[1];
    const float* wi    = (const float*)d_in[2];
    const float* bias  = (const float*)d_in[3];
    const float* lin_w = (const float*)d_in[4];
    const float* lin_b = (const float*)d_in[5];
    float* out = (float*)d_out;

    (void)in_sizes; (void)n_in; (void)out_size;

    const int kgemm_smem = (NHID * WPITCH + NHID * 64) * 4;   // 67584 B
    cudaFuncSetAttribute(kgemm,  cudaFuncAttributeMaxDynamicSharedMemorySize, kgemm_smem);
    cudaFuncSetAttribute(ksmall, cudaFuncAttributeMaxDynamicSharedMemorySize, 49280);

    kmodes<<<dim3(32, 8, 2), 128>>>(x, wr, wi);
    kgemm<<<dim3(1024, 2), 256, kgemm_smem>>>(bias, lin_w, lin_b);
    kwrite<<<dim3(64, 128, 4), 256>>>(out);
    ksmall<<<128, 256, 49280>>>(lin_w, out);
}

// round 8
// speedup vs baseline: 1.5663x; 1.5663x over previous
#include <cuda_runtime.h>
#include <math.h>

#define NBATCH 4
#define NHID   128
#define NCOL   65536
#define NMODE  256
#define NHS    8          // h-split for kmodes

// Scratch (allocation-free rule: device globals)
__device__ __align__(16) float g_yp[NHS * 2 * NBATCH * NHID * NMODE]; // 32 MB partials
__device__ __align__(16) float g_y[2 * NBATCH * NHID * NMODE];        // 1 MB reduced
__device__ __align__(16) float g_c[NHID * NMODE];                     // c + lin_b (raw)

__device__ __forceinline__ float gelu_exact(float v) {
    return 0.5f * v * (1.0f + erff(v * 0.70710678118654752440f));
}

// ---- packed f32x2 helpers (SASS FFMA2; PTX-only path on sm_103a) ----------
__device__ __forceinline__ unsigned long long pack2_dup(float v) {
    unsigned long long r;
    unsigned int u = __float_as_uint(v);
    asm("mov.b64 %0, {%1, %1};" : "=l"(r) : "r"(u));
    return r;
}
__device__ __forceinline__ void fma2(unsigned long long& d,
                                     unsigned long long a, unsigned long long b) {
    asm("fma.rn.f32x2 %0, %1, %2, %0;" : "+l"(d) : "l"(a), "l"(b));
}
__device__ __forceinline__ float2 unpack2(unsigned long long v) {
    unsigned int lo, hi;
    asm("mov.b64 {%0, %1}, %2;" : "=r"(lo), "=r"(hi) : "l"(v));
    return make_float2(__uint_as_float(lo), __uint_as_float(hi));
}

// ---------------------------------------------------------------------------
// Kernel A (R3-identical, measured 17.2us): per-mode GEMM, h split 8 ways.
//  g_yp[hs][ri][b][k][m] = sum_{h in chunk} x[b,h,m] * w_{ri}[h,k,m]
// grid (64 = 8 kb * 8 hs, 8 mb, 2 ri) = 1024 CTAs, 128 threads.
// ---------------------------------------------------------------------------
__global__ void __launch_bounds__(128) kmodes(const float* __restrict__ x,
                                              const float* __restrict__ wr,
                                              const float* __restrict__ wi) {
    __shared__ float xs[NBATCH * 16 * 32];    // 8 KB
    const int kb = blockIdx.x >> 3, hs = blockIdx.x & 7;
    const int mb = blockIdx.y, ri = blockIdx.z;
    const float* w = ri ? wi : wr;
    const int m0 = mb * 32, k0 = kb * 16, h0 = hs * 16;
    const int tid = threadIdx.x;

    for (int i = tid; i < NBATCH * 16 * 8; i += 128) {
        int j = i & 7;
        int bh = i >> 3;                 // b*16 + h
        int b = bh >> 4, h = bh & 15;
        float4 v = *reinterpret_cast<const float4*>(
            x + (size_t)(b * NHID + h0 + h) * NCOL + m0 + j * 4);
        *reinterpret_cast<float4*>(xs + bh * 32 + j * 4) = v;
    }
    __syncthreads();

    const int kl = tid & 15;      // 16 k per CTA
    const int mg = tid >> 4;      // 8 m-quads
    const int k  = k0 + kl;
    const int mm = mg * 4;

    float a[NBATCH][4];
#pragma unroll
    for (int b = 0; b < NBATCH; b++)
#pragma unroll
        for (int j = 0; j < 4; j++) a[b][j] = 0.f;

    const float* wp = w + (size_t)h0 * NHID * NMODE + (size_t)k * NMODE + m0 + mm;
#pragma unroll 8
    for (int h = 0; h < 16; h++) {
        float4 wv = __ldg(reinterpret_cast<const float4*>(wp + (size_t)h * NHID * NMODE));
#pragma unroll
        for (int b = 0; b < NBATCH; b++) {
            float4 xv = *reinterpret_cast<const float4*>(xs + (b * 16 + h) * 32 + mm);
            a[b][0] += xv.x * wv.x;
            a[b][1] += xv.y * wv.y;
            a[b][2] += xv.z * wv.z;
            a[b][3] += xv.w * wv.w;
        }
    }
#pragma unroll
    for (int b = 0; b < NBATCH; b++) {
        float4 v = make_float4(a[b][0], a[b][1], a[b][2], a[b][3]);
        *reinterpret_cast<float4*>(
            &g_yp[(((hs * 2 + ri) * NBATCH + b) * NHID + k) * NMODE + m0 + mm]) = v;
    }
}

// ---------------------------------------------------------------------------
// Kernel R: reduce the 8 h-partials with full parallelism (36 MB streamed).
//  g_y[i] = sum_hs g_yp[hs][i]   over 2*4*128*256 = 256Ki floats (64Ki float4)
// grid 256 CTAs x 256 threads, 1 float4 each, 8 independent LDGs (MLP=8).
// ---------------------------------------------------------------------------
__global__ void __launch_bounds__(256) kreduce() {
    const int i4 = blockIdx.x * 256 + threadIdx.x;     // float4 index
    const int STRIDE4 = 2 * NBATCH * NHID * NMODE / 4; // 65536 float4 per slice
    float4 v[NHS];
#pragma unroll
    for (int s = 0; s < NHS; s++)
        v[s] = *reinterpret_cast<const float4*>(&g_yp[(s * STRIDE4 + i4) * 4]);
    float4 acc = v[0];
#pragma unroll
    for (int s = 1; s < NHS; s++) {
        acc.x += v[s].x; acc.y += v[s].y; acc.z += v[s].z; acc.w += v[s].w;
    }
    *reinterpret_cast<float4*>(&g_y[i4 * 4]) = acc;
}

// ---------------------------------------------------------------------------
// Kernel B (fused, k-split): c[k,n] = sum_h lin_w[k,h]*bias[h,n] via FFMA2.
//   n >= 256: out[b,k,n,(0,1)] = (gelu(c+lin_b[k]), 0) for all 4 b
//   n <  256: g_c[k,n] = c + lin_b[k]
// grid (1024 nb, 2 kb) = 2048 CTAs, 256 threads (16 kt x 16 nt),
// 4k (2 packed pairs) x 4n per thread. 67.6 KB smem -> 3 CTAs/SM, 24 warps.
// ---------------------------------------------------------------------------
#define WPITCH 68   // 64 k-cols + pad (272 B rows, 16 B aligned)
__global__ void __launch_bounds__(256, 3) kmain(const float* __restrict__ bias,
                                                const float* __restrict__ lin_w,
                                                const float* __restrict__ lin_b,
                                                float* __restrict__ out) {
    extern __shared__ float sm[];
    float* wT = sm;                      // [h][k(64)] pitch 68
    float* sb = sm + NHID * WPITCH;      // [h][64]
    __shared__ float slb[64];

    const int tid = threadIdx.x;
    const int n_base = blockIdx.x * 64;
    const int kbase  = blockIdx.y * 64;

    for (int i = tid; i < 64 * NHID; i += 256) {
        int h = i & 127, k = i >> 7;
        wT[h * WPITCH + k] = lin_w[(kbase + k) * NHID + h];
    }
    if (tid < 64) slb[tid] = lin_b[kbase + tid];
    for (int i = tid; i < NHID * 16; i += 256) {
        int h = i >> 4, j = i & 15;
        float4 v = *reinterpret_cast<const float4*>(bias + (size_t)h * NCOL + n_base + j * 4);
        *reinterpret_cast<float4*>(sb + h * 64 + j * 4) = v;
    }
    __syncthreads();

    const int kt = tid >> 4;     // 0..15 -> 4 k each (2 packed pairs)
    const int nt = tid & 15;     // 0..15 -> 4 n each

    unsigned long long acc2[2][4];   // [k-pair][n]
#pragma unroll
    for (int p = 0; p < 2; p++)
#pragma unroll
        for (int j = 0; j < 4; j++) acc2[p][j] = 0ULL;

    const float* wrow = wT + kt * 4;
    const float* bp = sb + nt * 4;
#pragma unroll 4
    for (int h = 0; h < NHID; h++) {
        float4 bv = *reinterpret_cast<const float4*>(bp + h * 64);
        ulonglong2 wA = *reinterpret_cast<const ulonglong2*>(wrow + h * WPITCH);
        unsigned long long bn0 = pack2_dup(bv.x);
        unsigned long long bn1 = pack2_dup(bv.y);
        unsigned long long bn2 = pack2_dup(bv.z);
        unsigned long long bn3 = pack2_dup(bv.w);
        fma2(acc2[0][0], wA.x, bn0); fma2(acc2[0][1], wA.x, bn1);
        fma2(acc2[0][2], wA.x, bn2); fma2(acc2[0][3], wA.x, bn3);
        fma2(acc2[1][0], wA.y, bn0); fma2(acc2[1][1], wA.y, bn1);
        fma2(acc2[1][2], wA.y, bn2); fma2(acc2[1][3], wA.y, bn3);
    }

    const int n0 = n_base + nt * 4;
    if (n_base >= NMODE) {
#pragma unroll
        for (int p = 0; p < 2; p++) {
            int kk = kt * 4 + 2 * p;
            float lb0 = slb[kk], lb1 = slb[kk + 1];
            float2 a0 = unpack2(acc2[p][0]);
            float2 a1 = unpack2(acc2[p][1]);
            float2 a2 = unpack2(acc2[p][2]);
            float2 a3 = unpack2(acc2[p][3]);
            float4 lo0 = make_float4(gelu_exact(a0.x + lb0), 0.f, gelu_exact(a1.x + lb0), 0.f);
            float4 hi0 = make_float4(gelu_exact(a2.x + lb0), 0.f, gelu_exact(a3.x + lb0), 0.f);
            float4 lo1 = make_float4(gelu_exact(a0.y + lb1), 0.f, gelu_exact(a1.y + lb1), 0.f);
            float4 hi1 = make_float4(gelu_exact(a2.y + lb1), 0.f, gelu_exact(a3.y + lb1), 0.f);
            const int k0 = kbase + kk;
#pragma unroll
            for (int b = 0; b < NBATCH; b++) {
                float* op0 = out + 2 * ((size_t)(b * NHID + k0) * NCOL + n0);
                float* op1 = op0 + 2 * NCOL;
                __stcs(reinterpret_cast<float4*>(op0),     lo0);
                __stcs(reinterpret_cast<float4*>(op0 + 4), hi0);
                __stcs(reinterpret_cast<float4*>(op1),     lo1);
                __stcs(reinterpret_cast<float4*>(op1 + 4), hi1);
            }
        }
    } else {
#pragma unroll
        for (int p = 0; p < 2; p++) {
            int kk = kt * 4 + 2 * p;
            float lb0 = slb[kk], lb1 = slb[kk + 1];
            float2 a0 = unpack2(acc2[p][0]);
            float2 a1 = unpack2(acc2[p][1]);
            float2 a2 = unpack2(acc2[p][2]);
            float2 a3 = unpack2(acc2[p][3]);
            *reinterpret_cast<float4*>(&g_c[(kbase + kk) * NMODE + n0]) =
                make_float4(a0.x + lb0, a1.x + lb0, a2.x + lb0, a3.x + lb0);
            *reinterpret_cast<float4*>(&g_c[(kbase + kk + 1) * NMODE + n0]) =
                make_float4(a0.y + lb1, a1.y + lb1, a2.y + lb1, a3.y + lb1);
        }
    }
}

// ---------------------------------------------------------------------------
// Kernel C: n < 256 region, reads reduced g_y (1 MB, L2-hot).
//   out[b,k,n,0] = gelu(sum_h lin_w[k,h]*y_r + g_c[k,n]); out[...,1] = gelu(..y_i)
// grid 128 = (8 m-tiles of 32) x (4 b) x (4 k-blocks of 32), 256 threads
// ---------------------------------------------------------------------------
__global__ void __launch_bounds__(256) ksmall(const float* __restrict__ lin_w,
                                              float* __restrict__ out) {
    extern __shared__ float smc[];
    float* sW = smc;               // [32][129]
    float* sy = smc + 32 * 129;    // [ri*128+h][32]
    const int bx = blockIdx.x;
    const int mt = bx & 7, b = (bx >> 3) & 3, kb = bx >> 5;
    const int tid = threadIdx.x;
    const int m0 = mt * 32;

    for (int i = tid; i < 32 * NHID; i += 256) {
        int h = i & 127, r = i >> 7;
        sW[r * 129 + h] = lin_w[(kb * 32 + r) * NHID + h];
    }
    for (int i = tid; i < 2 * NHID * 8; i += 256) {
        int j = i & 7;
        int rh = i >> 3;                 // ri*128 + h
        int ri = rh >> 7, h = rh & 127;
        float4 v = *reinterpret_cast<const float4*>(
            &g_y[((ri * NBATCH + b) * NHID + h) * NMODE + m0 + j * 4]);
        *reinterpret_cast<float4*>(sy + rh * 32 + j * 4) = v;
    }
    __syncthreads();

    const int kl = tid >> 3;   // 0..31
    const int ng = tid & 7;
    const int k = kb * 32 + kl;

    float ar[4] = {0.f, 0.f, 0.f, 0.f};
    float ai[4] = {0.f, 0.f, 0.f, 0.f};
    const float* wp  = sW + kl * 129;
    const float* yrp = sy + ng * 4;
    const float* yip = sy + NHID * 32 + ng * 4;
#pragma unroll 4
    for (int h = 0; h < NHID; h++) {
        float w = wp[h];
        float4 r4 = *reinterpret_cast<const float4*>(yrp + h * 32);
        float4 i4 = *reinterpret_cast<const float4*>(yip + h * 32);
        ar[0] += w * r4.x; ar[1] += w * r4.y; ar[2] += w * r4.z; ar[3] += w * r4.w;
        ai[0] += w * i4.x; ai[1] += w * i4.y; ai[2] += w * i4.z; ai[3] += w * i4.w;
    }
    const int n0 = m0 + ng * 4;
    float4 cv = *reinterpret_cast<const float4*>(&g_c[k * NMODE + n0]);
    float4 lo = make_float4(gelu_exact(ar[0] + cv.x), gelu_exact(ai[0]),
                            gelu_exact(ar[1] + cv.y), gelu_exact(ai[1]));
    float4 hi = make_float4(gelu_exact(ar[2] + cv.z), gelu_exact(ai[2]),
                            gelu_exact(ar[3] + cv.w), gelu_exact(ai[3]));
    float* op = out + 2 * ((size_t)(b * NHID + k) * NCOL + n0);
    *reinterpret_cast<float4*>(op)     = lo;
    *reinterpret_cast<float4*>(op + 4) = hi;
}

// ---------------------------------------------------------------------------
extern "C" void kernel_launch(void* const* d_in, const int* in_sizes, int n_in,
                              void* d_out, int out_size) {
    const float* x     = (const float*)d_in[0];
    const float* wr    = (const float*)d_in[1];
    const float* wi    = (const float*)d_in[2];
    const float* bias  = (const float*)d_in[3];
    const float* lin_w = (const float*)d_in[4];
    const float* lin_b = (const float*)d_in[5];
    float* out = (float*)d_out;

    (void)in_sizes; (void)n_in; (void)out_size;

    const int kmain_smem = (NHID * WPITCH + NHID * 64) * 4;   // 67584 B
    cudaFuncSetAttribute(kmain,  cudaFuncAttributeMaxDynamicSharedMemorySize, kmain_smem);
    cudaFuncSetAttribute(ksmall, cudaFuncAttributeMaxDynamicSharedMemorySize, 49280);

    kmodes<<<dim3(64, 8, 2), 128>>>(x, wr, wi);
    kreduce<<<256, 256>>>();
    kmain<<<dim3(1024, 2), 256, kmain_smem>>>(bias, lin_w, lin_b, out);
    ksmall<<<128, 256, 49280>>>(lin_w, out);
}

// round 9
// speedup vs baseline: 1.6385x; 1.0461x over previous
#include <cuda_runtime.h>
#include <math.h>

#define NBATCH 4
#define NHID   128
#define NCOL   65536
#define NMODE  256
#define NHS    8          // h-split for kmodes

// Scratch (allocation-free rule: device globals)
__device__ __align__(16) float g_yp[NHS * 2 * NBATCH * NHID * NMODE]; // 32 MB partials
__device__ __align__(16) float g_y[2 * NBATCH * NHID * NMODE];        // 1 MB reduced
__device__ __align__(16) float g_c[NHID * NMODE];                     // c + lin_b (raw)

__device__ __forceinline__ float gelu_exact(float v) {
    return 0.5f * v * (1.0f + erff(v * 0.70710678118654752440f));
}

// ---- packed f32x2 helpers (SASS FFMA2; PTX-only path on sm_103a) ----------
__device__ __forceinline__ unsigned long long pack2_dup(float v) {
    unsigned long long r;
    unsigned int u = __float_as_uint(v);
    asm("mov.b64 %0, {%1, %1};" : "=l"(r) : "r"(u));
    return r;
}
__device__ __forceinline__ void fma2(unsigned long long& d,
                                     unsigned long long a, unsigned long long b) {
    asm("fma.rn.f32x2 %0, %1, %2, %0;" : "+l"(d) : "l"(a), "l"(b));
}
__device__ __forceinline__ float2 unpack2(unsigned long long v) {
    unsigned int lo, hi;
    asm("mov.b64 {%0, %1}, %2;" : "=r"(lo), "=r"(hi) : "l"(v));
    return make_float2(__uint_as_float(lo), __uint_as_float(hi));
}

// ---------------------------------------------------------------------------
// Kernel A (measured 17.2us): per-mode GEMM, h split 8 ways.
//  g_yp[hs][ri][b][k][m] = sum_{h in chunk} x[b,h,m] * w_{ri}[h,k,m]
// grid (64 = 8 kb * 8 hs, 8 mb, 2 ri) = 1024 CTAs, 128 threads.
// ---------------------------------------------------------------------------
__global__ void __launch_bounds__(128) kmodes(const float* __restrict__ x,
                                              const float* __restrict__ wr,
                                              const float* __restrict__ wi) {
    __shared__ float xs[NBATCH * 16 * 32];    // 8 KB
    const int kb = blockIdx.x >> 3, hs = blockIdx.x & 7;
    const int mb = blockIdx.y, ri = blockIdx.z;
    const float* w = ri ? wi : wr;
    const int m0 = mb * 32, k0 = kb * 16, h0 = hs * 16;
    const int tid = threadIdx.x;

    for (int i = tid; i < NBATCH * 16 * 8; i += 128) {
        int j = i & 7;
        int bh = i >> 3;                 // b*16 + h
        int b = bh >> 4, h = bh & 15;
        float4 v = *reinterpret_cast<const float4*>(
            x + (size_t)(b * NHID + h0 + h) * NCOL + m0 + j * 4);
        *reinterpret_cast<float4*>(xs + bh * 32 + j * 4) = v;
    }
    __syncthreads();

    const int kl = tid & 15;      // 16 k per CTA
    const int mg = tid >> 4;      // 8 m-quads
    const int k  = k0 + kl;
    const int mm = mg * 4;

    float a[NBATCH][4];
#pragma unroll
    for (int b = 0; b < NBATCH; b++)
#pragma unroll
        for (int j = 0; j < 4; j++) a[b][j] = 0.f;

    const float* wp = w + (size_t)h0 * NHID * NMODE + (size_t)k * NMODE + m0 + mm;
#pragma unroll 8
    for (int h = 0; h < 16; h++) {
        float4 wv = __ldg(reinterpret_cast<const float4*>(wp + (size_t)h * NHID * NMODE));
#pragma unroll
        for (int b = 0; b < NBATCH; b++) {
            float4 xv = *reinterpret_cast<const float4*>(xs + (b * 16 + h) * 32 + mm);
            a[b][0] += xv.x * wv.x;
            a[b][1] += xv.y * wv.y;
            a[b][2] += xv.z * wv.z;
            a[b][3] += xv.w * wv.w;
        }
    }
#pragma unroll
    for (int b = 0; b < NBATCH; b++) {
        float4 v = make_float4(a[b][0], a[b][1], a[b][2], a[b][3]);
        *reinterpret_cast<float4*>(
            &g_yp[(((hs * 2 + ri) * NBATCH + b) * NHID + k) * NMODE + m0 + mm]) = v;
    }
}

// ---------------------------------------------------------------------------
// Kernel R: reduce the 8 h-partials (36 MB streamed, MLP=8).
// ---------------------------------------------------------------------------
__global__ void __launch_bounds__(256) kreduce() {
    const int i4 = blockIdx.x * 256 + threadIdx.x;     // float4 index
    const int STRIDE4 = 2 * NBATCH * NHID * NMODE / 4; // 65536 float4 per slice
    float4 v[NHS];
#pragma unroll
    for (int s = 0; s < NHS; s++)
        v[s] = *reinterpret_cast<const float4*>(&g_yp[(s * STRIDE4 + i4) * 4]);
    float4 acc = v[0];
#pragma unroll
    for (int s = 1; s < NHS; s++) {
        acc.x += v[s].x; acc.y += v[s].y; acc.z += v[s].z; acc.w += v[s].w;
    }
    *reinterpret_cast<float4*>(&g_y[i4 * 4]) = acc;
}

// ---------------------------------------------------------------------------
// Kernel B (fused, 4 CTAs/SM): c[k,n] = sum_h lin_w[k,h]*bias[h,n] via FFMA2.
//   n >= 256: out[b,k,n,(0,1)] = (gelu(c+lin_b[k]), 0) for all 4 b
//   n <  256: g_c[k,n] = c + lin_b[k]
// grid (2048 nb of 32 cols, 2 kb of 64) = 4096 CTAs, 256 threads
// (16 kt x 16 nt), 4k (2 packed pairs) x 2n per thread. 51.2 KB smem.
// ---------------------------------------------------------------------------
#define WPITCH 68   // 64 k-cols + pad (272 B rows, 16 B aligned)
__global__ void __launch_bounds__(256, 4) kmain(const float* __restrict__ bias,
                                                const float* __restrict__ lin_w,
                                                const float* __restrict__ lin_b,
                                                float* __restrict__ out) {
    extern __shared__ float sm[];
    float* wT = sm;                      // [h][k(64)] pitch 68
    float* sb = sm + NHID * WPITCH;      // [h][32]
    __shared__ float slb[64];

    const int tid = threadIdx.x;
    const int n_base = blockIdx.x * 32;
    const int kbase  = blockIdx.y * 64;

    for (int i = tid; i < 64 * NHID; i += 256) {
        int h = i & 127, k = i >> 7;
        wT[h * WPITCH + k] = lin_w[(kbase + k) * NHID + h];
    }
    if (tid < 64) slb[tid] = lin_b[kbase + tid];
    for (int i = tid; i < NHID * 8; i += 256) {
        int h = i >> 3, j = i & 7;
        float4 v = *reinterpret_cast<const float4*>(bias + (size_t)h * NCOL + n_base + j * 4);
        *reinterpret_cast<float4*>(sb + h * 32 + j * 4) = v;
    }
    __syncthreads();

    const int kt = tid >> 4;     // 0..15 -> 4 k each (2 packed pairs)
    const int nt = tid & 15;     // 0..15 -> 2 n each

    unsigned long long acc2[2][2];   // [k-pair][n]
#pragma unroll
    for (int p = 0; p < 2; p++)
#pragma unroll
        for (int j = 0; j < 2; j++) acc2[p][j] = 0ULL;

    const float* wrow = wT + kt * 4;
    const float* bp = sb + nt * 2;
#pragma unroll 4
    for (int h = 0; h < NHID; h++) {
        float2 bv = *reinterpret_cast<const float2*>(bp + h * 32);
        ulonglong2 wA = *reinterpret_cast<const ulonglong2*>(wrow + h * WPITCH);
        unsigned long long bn0 = pack2_dup(bv.x);
        unsigned long long bn1 = pack2_dup(bv.y);
        fma2(acc2[0][0], wA.x, bn0); fma2(acc2[0][1], wA.x, bn1);
        fma2(acc2[1][0], wA.y, bn0); fma2(acc2[1][1], wA.y, bn1);
    }

    const int n0 = n_base + nt * 2;
    if (n_base >= NMODE) {
#pragma unroll
        for (int p = 0; p < 2; p++) {
            int kk = kt * 4 + 2 * p;
            float lb0 = slb[kk], lb1 = slb[kk + 1];
            float2 a0 = unpack2(acc2[p][0]);   // (k=kk, k=kk+1) at n0
            float2 a1 = unpack2(acc2[p][1]);   // (k=kk, k=kk+1) at n0+1
            float4 v0 = make_float4(gelu_exact(a0.x + lb0), 0.f, gelu_exact(a1.x + lb0), 0.f);
            float4 v1 = make_float4(gelu_exact(a0.y + lb1), 0.f, gelu_exact(a1.y + lb1), 0.f);
            const int k0 = kbase + kk;
#pragma unroll
            for (int b = 0; b < NBATCH; b++) {
                float* op0 = out + 2 * ((size_t)(b * NHID + k0) * NCOL + n0);
                __stcs(reinterpret_cast<float4*>(op0),            v0);
                __stcs(reinterpret_cast<float4*>(op0 + 2 * NCOL), v1);
            }
        }
    } else {
#pragma unroll
        for (int p = 0; p < 2; p++) {
            int kk = kt * 4 + 2 * p;
            float lb0 = slb[kk], lb1 = slb[kk + 1];
            float2 a0 = unpack2(acc2[p][0]);
            float2 a1 = unpack2(acc2[p][1]);
            *reinterpret_cast<float2*>(&g_c[(kbase + kk) * NMODE + n0]) =
                make_float2(a0.x + lb0, a1.x + lb0);
            *reinterpret_cast<float2*>(&g_c[(kbase + kk + 1) * NMODE + n0]) =
                make_float2(a0.y + lb1, a1.y + lb1);
        }
    }
}

// ---------------------------------------------------------------------------
// Kernel C: n < 256 region, reads reduced g_y (1 MB, L2-hot).
//   out[b,k,n,0] = gelu(sum_h lin_w[k,h]*y_r + g_c[k,n]); out[...,1] = gelu(..y_i)
// grid (8 mt of 32, 4 b, 8 kb of 16) = 256 CTAs, 256 threads
// (16 kl x 16 ng of 2n). ~2 CTAs/SM for latency hiding.
// ---------------------------------------------------------------------------
__global__ void __launch_bounds__(256) ksmall(const float* __restrict__ lin_w,
                                              float* __restrict__ out) {
    __shared__ float sW[16 * 129];      // [k(16)][h] pitch 129
    __shared__ float sy[2 * NHID * 32]; // [ri*128+h][32]
    const int mt = blockIdx.x, b = blockIdx.y, kb = blockIdx.z;
    const int tid = threadIdx.x;
    const int m0 = mt * 32;

    for (int i = tid; i < 16 * NHID; i += 256) {
        int h = i & 127, r = i >> 7;
        sW[r * 129 + h] = lin_w[(kb * 16 + r) * NHID + h];
    }
    for (int i = tid; i < 2 * NHID * 8; i += 256) {
        int j = i & 7;
        int rh = i >> 3;                 // ri*128 + h
        int ri = rh >> 7, h = rh & 127;
        float4 v = *reinterpret_cast<const float4*>(
            &g_y[((ri * NBATCH + b) * NHID + h) * NMODE + m0 + j * 4]);
        *reinterpret_cast<float4*>(sy + rh * 32 + j * 4) = v;
    }
    __syncthreads();

    const int kl = tid >> 4;   // 0..15
    const int ng = tid & 15;   // 0..15, 2 n each
    const int k = kb * 16 + kl;

    float ar0 = 0.f, ar1 = 0.f, ai0 = 0.f, ai1 = 0.f;
    const float* wp  = sW + kl * 129;
    const float* yrp = sy + ng * 2;
    const float* yip = sy + NHID * 32 + ng * 2;
#pragma unroll 4
    for (int h = 0; h < NHID; h++) {
        float w = wp[h];
        float2 r2 = *reinterpret_cast<const float2*>(yrp + h * 32);
        float2 i2 = *reinterpret_cast<const float2*>(yip + h * 32);
        ar0 += w * r2.x; ar1 += w * r2.y;
        ai0 += w * i2.x; ai1 += w * i2.y;
    }
    const int n0 = m0 + ng * 2;
    float2 cv = *reinterpret_cast<const float2*>(&g_c[k * NMODE + n0]);
    float4 o = make_float4(gelu_exact(ar0 + cv.x), gelu_exact(ai0),
                           gelu_exact(ar1 + cv.y), gelu_exact(ai1));
    float* op = out + 2 * ((size_t)(b * NHID + k) * NCOL + n0);
    *reinterpret_cast<float4*>(op) = o;
}

// ---------------------------------------------------------------------------
extern "C" void kernel_launch(void* const* d_in, const int* in_sizes, int n_in,
                              void* d_out, int out_size) {
    const float* x     = (const float*)d_in[0];
    const float* wr    = (const float*)d_in[1];
    const float* wi    = (const float*)d_in[2];
    const float* bias  = (const float*)d_in[3];
    const float* lin_w = (const float*)d_in[4];
    const float* lin_b = (const float*)d_in[5];
    float* out = (float*)d_out;

    (void)in_sizes; (void)n_in; (void)out_size;

    const int kmain_smem = (NHID * WPITCH + NHID * 32) * 4;   // 51200 B
    cudaFuncSetAttribute(kmain, cudaFuncAttributeMaxDynamicSharedMemorySize, kmain_smem);

    kmodes<<<dim3(64, 8, 2), 128>>>(x, wr, wi);
    kreduce<<<256, 256>>>();
    kmain<<<dim3(2048, 2), 256, kmain_smem>>>(bias, lin_w, lin_b, out);
    ksmall<<<dim3(8, 4, 8), 256>>>(lin_w, out);
}